// round 2
// baseline (speedup 1.0000x reference)
#include <cuda_runtime.h>
#include <math.h>

// Problem constants
#define CB 4
#define CT 1024
#define CD 1024
#define CH 16
#define CDK 64
#define CM (CB * CT)   // 4096 rows

// Scratch (device globals: allocation-free)
__device__ float g_Q[CB * CH * CT * CDK];   // [B,H,T,DK]
__device__ float g_K[CB * CH * CT * CDK];
__device__ float g_V[CB * CH * CT * CDK];
__device__ float g_A[CB * CT * CD];         // attention output, [B,T,D]

// ----------------------------------------------------------------------------
// Projection GEMM: Y[m,n] = sum_k X[m,k] * W[n,k] + bias[n]
// 128x128 tile, K-step 16, 256 threads (16x16), 8x8 microtile (split 4+4).
// qkv_layout==1: write Y as [B,H,T,DK] (head = n>>6); else plain [M,N].
// ----------------------------------------------------------------------------
__global__ __launch_bounds__(256) void proj_kernel(
    const float* __restrict__ X, const float* __restrict__ W,
    const float* __restrict__ bias, float* __restrict__ Y, int qkv_layout)
{
    __shared__ float Xs[16][128];   // [k][m]
    __shared__ float Ws[16][128];   // [k][n]

    const int tx = threadIdx.x, ty = threadIdx.y;   // 16x16
    const int tid = ty * 16 + tx;
    const int m0 = blockIdx.y * 128;
    const int n0 = blockIdx.x * 128;

    // loader mapping: 512 float4 per tile per matrix; 2 per thread
    const int lr0 = tid >> 2;        // rows 0..63   (idx = tid)
    const int lq0 = tid & 3;
    const int lr1 = (tid + 256) >> 2; // rows 64..127 (idx = tid+256)
    const int lq1 = (tid + 256) & 3;

    float acc[8][8] = {};

    for (int k0 = 0; k0 < CD; k0 += 16) {
        float4 xa = *(const float4*)(X + (size_t)(m0 + lr0) * CD + k0 + lq0 * 4);
        float4 xb = *(const float4*)(X + (size_t)(m0 + lr1) * CD + k0 + lq1 * 4);
        float4 wa = *(const float4*)(W + (size_t)(n0 + lr0) * CD + k0 + lq0 * 4);
        float4 wb = *(const float4*)(W + (size_t)(n0 + lr1) * CD + k0 + lq1 * 4);
        Xs[lq0 * 4 + 0][lr0] = xa.x; Xs[lq0 * 4 + 1][lr0] = xa.y;
        Xs[lq0 * 4 + 2][lr0] = xa.z; Xs[lq0 * 4 + 3][lr0] = xa.w;
        Xs[lq1 * 4 + 0][lr1] = xb.x; Xs[lq1 * 4 + 1][lr1] = xb.y;
        Xs[lq1 * 4 + 2][lr1] = xb.z; Xs[lq1 * 4 + 3][lr1] = xb.w;
        Ws[lq0 * 4 + 0][lr0] = wa.x; Ws[lq0 * 4 + 1][lr0] = wa.y;
        Ws[lq0 * 4 + 2][lr0] = wa.z; Ws[lq0 * 4 + 3][lr0] = wa.w;
        Ws[lq1 * 4 + 0][lr1] = wb.x; Ws[lq1 * 4 + 1][lr1] = wb.y;
        Ws[lq1 * 4 + 2][lr1] = wb.z; Ws[lq1 * 4 + 3][lr1] = wb.w;
        __syncthreads();

        #pragma unroll
        for (int k = 0; k < 16; ++k) {
            float4 a0 = *(const float4*)&Xs[k][ty * 4];
            float4 a1 = *(const float4*)&Xs[k][64 + ty * 4];
            float4 b0 = *(const float4*)&Ws[k][tx * 4];
            float4 b1 = *(const float4*)&Ws[k][64 + tx * 4];
            float ar[8] = {a0.x, a0.y, a0.z, a0.w, a1.x, a1.y, a1.z, a1.w};
            float br[8] = {b0.x, b0.y, b0.z, b0.w, b1.x, b1.y, b1.z, b1.w};
            #pragma unroll
            for (int i = 0; i < 8; ++i)
                #pragma unroll
                for (int j = 0; j < 8; ++j)
                    acc[i][j] += ar[i] * br[j];
        }
        __syncthreads();
    }

    float4 bv0 = *(const float4*)(bias + n0 + tx * 4);
    float4 bv1 = *(const float4*)(bias + n0 + 64 + tx * 4);
    float bb[8] = {bv0.x, bv0.y, bv0.z, bv0.w, bv1.x, bv1.y, bv1.z, bv1.w};

    #pragma unroll
    for (int i = 0; i < 8; ++i) {
        int m = m0 + (i < 4 ? ty * 4 + i : 64 + ty * 4 + (i - 4));
        #pragma unroll
        for (int jh = 0; jh < 2; ++jh) {            // two float4 column groups
            int ncol = (jh == 0 ? tx * 4 : 64 + tx * 4);
            float4 o;
            o.x = acc[i][jh * 4 + 0] + bb[jh * 4 + 0];
            o.y = acc[i][jh * 4 + 1] + bb[jh * 4 + 1];
            o.z = acc[i][jh * 4 + 2] + bb[jh * 4 + 2];
            o.w = acc[i][jh * 4 + 3] + bb[jh * 4 + 3];
            if (qkv_layout) {
                int b = m >> 10;                    // m / T
                int t = m & 1023;                   // m % T
                int n = n0 + ncol;
                int h = n >> 6;
                int dk = n & 63;
                float* dst = Y + ((size_t)(b * CH + h) * CT + t) * CDK + dk;
                *(float4*)dst = o;
            } else {
                *(float4*)(Y + (size_t)m * CD + n0 + ncol) = o;
            }
        }
    }
}

// ----------------------------------------------------------------------------
// Flash-style causal attention with spatial-distance bias.
// Grid: (T/64 q-tiles, B*H). 256 threads (16x16). Dynamic smem.
// scores = QK^T/8 - |alpha|*dist; causal mask via index compare (mask == tril).
// ----------------------------------------------------------------------------
#define QS_STRIDE 68   // 64 + 4 pad floats (17 float4) — conflict-free K reads
#define ATTN_SMEM ((2 * 64 * QS_STRIDE + 64 * 64 + 3 * 64) * (int)sizeof(float))

__global__ __launch_bounds__(256) void attn_kernel(
    const float* __restrict__ dist, const float* __restrict__ swp,
    const float* __restrict__ Q, const float* __restrict__ K,
    const float* __restrict__ V, float* __restrict__ Aout)
{
    extern __shared__ float sm[];
    float* Qs   = sm;                       // 64 x 68
    float* KVs  = sm + 64 * QS_STRIDE;      // 64 x 68 (K, then reused for V)
    float* S    = sm + 2 * 64 * QS_STRIDE;  // 64 x 64
    float* mrow = S + 64 * 64;
    float* lrow = mrow + 64;
    float* crow = lrow + 64;

    const int tx = threadIdx.x, ty = threadIdx.y;
    const int tid = ty * 16 + tx;
    const int qt = blockIdx.x;
    const int bh = blockIdx.y;              // b*H + h
    const int b  = bh >> 4;
    const int h  = bh & 15;
    const int qbase = qt * 64;
    const float alphaAbs = fabsf(swp[0]);

    // Load Q tile [64 x 64] into padded smem
    const float* Qp = Q + ((size_t)bh * CT + qbase) * CDK;
    #pragma unroll
    for (int it = 0; it < 4; ++it) {
        int idx = tid + it * 256;           // 0..1023 float4 slots
        int r = idx >> 4, d4 = idx & 15;
        *(float4*)(Qs + r * QS_STRIDE + d4 * 4) =
            *(const float4*)(Qp + r * CDK + d4 * 4);
    }
    if (tid < 64) { mrow[tid] = -1e30f; lrow[tid] = 0.0f; }

    float acc_o[4][4] = {};
    __syncthreads();

    for (int jt = 0; jt <= qt; ++jt) {
        const int kbase = jt * 64;

        // Load K tile
        const float* Kp = K + ((size_t)bh * CT + kbase) * CDK;
        #pragma unroll
        for (int it = 0; it < 4; ++it) {
            int idx = tid + it * 256;
            int r = idx >> 4, d4 = idx & 15;
            *(float4*)(KVs + r * QS_STRIDE + d4 * 4) =
                *(const float4*)(Kp + r * CDK + d4 * 4);
        }
        __syncthreads();

        // S = Q K^T  (rows: ty + i*16, cols: tx + j*16)
        float accs[4][4] = {};
        #pragma unroll
        for (int d4 = 0; d4 < 16; ++d4) {
            float4 a[4], bb[4];
            #pragma unroll
            for (int i = 0; i < 4; ++i)
                a[i] = *(const float4*)(Qs + (ty + i * 16) * QS_STRIDE + d4 * 4);
            #pragma unroll
            for (int j = 0; j < 4; ++j)
                bb[j] = *(const float4*)(KVs + (tx + j * 16) * QS_STRIDE + d4 * 4);
            #pragma unroll
            for (int i = 0; i < 4; ++i)
                #pragma unroll
                for (int j = 0; j < 4; ++j)
                    accs[i][j] += a[i].x * bb[j].x + a[i].y * bb[j].y
                                + a[i].z * bb[j].z + a[i].w * bb[j].w;
        }

        const bool diag = (jt == qt);
        #pragma unroll
        for (int i = 0; i < 4; ++i) {
            int qg = qbase + ty + i * 16;
            const float* drow = dist + ((size_t)b * CT + qg) * CT + kbase;
            #pragma unroll
            for (int j = 0; j < 4; ++j) {
                int c = tx + j * 16;
                float s = accs[i][j] * 0.125f - alphaAbs * drow[c];
                if (diag && (kbase + c) > qg) s = -1e30f;
                S[(ty + i * 16) * 64 + c] = s;
            }
        }
        __syncthreads();

        // Load V tile (KVs free: S compute was its only reader) + online softmax
        const float* Vp = V + ((size_t)bh * CT + kbase) * CDK;
        #pragma unroll
        for (int it = 0; it < 4; ++it) {
            int idx = tid + it * 256;
            int r = idx >> 4, d4 = idx & 15;
            *(float4*)(KVs + r * QS_STRIDE + d4 * 4) =
                *(const float4*)(Vp + r * CDK + d4 * 4);
        }
        {
            int w = tid >> 5, lane = tid & 31;   // warp w owns rows 8w..8w+7
            #pragma unroll
            for (int rr = 0; rr < 8; ++rr) {
                int r = w * 8 + rr;
                float s0 = S[r * 64 + lane];
                float s1 = S[r * 64 + 32 + lane];
                float mx = fmaxf(s0, s1);
                #pragma unroll
                for (int off = 16; off > 0; off >>= 1)
                    mx = fmaxf(mx, __shfl_xor_sync(0xffffffffu, mx, off));
                float mold = mrow[r];
                float mnew = fmaxf(mold, mx);
                float p0 = __expf(s0 - mnew);
                float p1 = __expf(s1 - mnew);
                float sum = p0 + p1;
                #pragma unroll
                for (int off = 16; off > 0; off >>= 1)
                    sum += __shfl_xor_sync(0xffffffffu, sum, off);
                S[r * 64 + lane] = p0;
                S[r * 64 + 32 + lane] = p1;
                if (lane == 0) {
                    float corr = __expf(mold - mnew);
                    crow[r] = corr;
                    lrow[r] = lrow[r] * corr + sum;
                    mrow[r] = mnew;
                }
            }
        }
        __syncthreads();

        // O = O*corr + P @ V
        float ci[4];
        #pragma unroll
        for (int i = 0; i < 4; ++i) ci[i] = crow[ty + i * 16];
        #pragma unroll
        for (int i = 0; i < 4; ++i)
            #pragma unroll
            for (int j = 0; j < 4; ++j) acc_o[i][j] *= ci[i];
        #pragma unroll
        for (int c = 0; c < 64; ++c) {
            float p[4], v[4];
            #pragma unroll
            for (int i = 0; i < 4; ++i) p[i] = S[(ty + i * 16) * 64 + c];
            #pragma unroll
            for (int j = 0; j < 4; ++j) v[j] = KVs[c * QS_STRIDE + tx + j * 16];
            #pragma unroll
            for (int i = 0; i < 4; ++i)
                #pragma unroll
                for (int j = 0; j < 4; ++j) acc_o[i][j] += p[i] * v[j];
        }
        __syncthreads();
    }

    // Final normalize + write to g_A in [B,T,D] layout (col = h*64 + c)
    float linv[4];
    #pragma unroll
    for (int i = 0; i < 4; ++i) linv[i] = 1.0f / lrow[ty + i * 16];
    #pragma unroll
    for (int i = 0; i < 4; ++i) {
        int t = qbase + ty + i * 16;
        float* dst = Aout + ((size_t)b * CT + t) * CD + h * CDK;
        #pragma unroll
        for (int j = 0; j < 4; ++j)
            dst[tx + j * 16] = acc_o[i][j] * linv[i];
    }
}

// ----------------------------------------------------------------------------
// Launch: QKV projections -> attention -> output projection
// Inputs (metadata order): x, s2_distances, mask, Wq, bq, Wk, bk, Wv, bv,
//                          Wo, bo, spatial_weight
// ----------------------------------------------------------------------------
extern "C" void kernel_launch(void* const* d_in, const int* in_sizes, int n_in,
                              void* d_out, int out_size)
{
    (void)in_sizes; (void)n_in; (void)out_size;
    const float* x    = (const float*)d_in[0];
    const float* dist = (const float*)d_in[1];
    // d_in[2] mask unused: reference mask is exactly causal tril, applied via index compare
    const float* Wq = (const float*)d_in[3];
    const float* bq = (const float*)d_in[4];
    const float* Wk = (const float*)d_in[5];
    const float* bk = (const float*)d_in[6];
    const float* Wv = (const float*)d_in[7];
    const float* bv = (const float*)d_in[8];
    const float* Wo = (const float*)d_in[9];
    const float* bo = (const float*)d_in[10];
    const float* sw = (const float*)d_in[11];

    float *pQ, *pK, *pV, *pA;
    cudaGetSymbolAddress((void**)&pQ, g_Q);
    cudaGetSymbolAddress((void**)&pK, g_K);
    cudaGetSymbolAddress((void**)&pV, g_V);
    cudaGetSymbolAddress((void**)&pA, g_A);

    dim3 blk(16, 16);
    dim3 gp(CD / 128, CM / 128);   // (8, 32)

    proj_kernel<<<gp, blk>>>(x, Wq, bq, pQ, 1);
    proj_kernel<<<gp, blk>>>(x, Wk, bk, pK, 1);
    proj_kernel<<<gp, blk>>>(x, Wv, bv, pV, 1);

    cudaFuncSetAttribute(attn_kernel, cudaFuncAttributeMaxDynamicSharedMemorySize, ATTN_SMEM);
    attn_kernel<<<dim3(CT / 64, CB * CH), blk, ATTN_SMEM>>>(dist, sw, pQ, pK, pV, pA);

    proj_kernel<<<gp, blk>>>(pA, Wo, bo, (float*)d_out, 0);
}

// round 5
// speedup vs baseline: 1.7547x; 1.7547x over previous
#include <cuda_runtime.h>
#include <cuda_bf16.h>
#include <math.h>
#include <cstdint>

// Problem constants
#define CB 4
#define CT 1024
#define CD 1024
#define CH 16
#define CDK 64
#define CM (CB * CT)   // 4096 rows

// ---------------------------------------------------------------------------
// Scratch (device globals: allocation-free)
// ---------------------------------------------------------------------------
__device__ __align__(16) float g_Q[CB * CH * CT * CDK];   // [B,H,T,DK]
__device__ __align__(16) float g_K[CB * CH * CT * CDK];
__device__ __align__(16) float g_V[CB * CH * CT * CDK];
__device__ __align__(16) float g_A[CB * CT * CD];         // attention out [B,T,D]
__device__ __align__(16) __nv_bfloat16 g_Xhi[CM * CD];    // activations hi/lo
__device__ __align__(16) __nv_bfloat16 g_Xlo[CM * CD];
__device__ __align__(16) __nv_bfloat16 g_Whi[CD * CD];    // current weight hi/lo
__device__ __align__(16) __nv_bfloat16 g_Wlo[CD * CD];

// ---------------------------------------------------------------------------
// Baseline-PTX helpers (all legal at compute_103: no arch-'a' features)
// ---------------------------------------------------------------------------
__device__ __forceinline__ uint32_t smem_to_u32(const void* p) {
    uint32_t a;
    asm("{ .reg .u64 t; cvta.to.shared.u64 t, %1; cvt.u32.u64 %0, t; }"
        : "=r"(a) : "l"(p));
    return a;
}
__device__ __forceinline__ void cp16(uint32_t saddr, const void* gptr) {
    asm volatile("cp.async.cg.shared.global [%0], [%1], 16;"
                 :: "r"(saddr), "l"(gptr));
}
#define CP_COMMIT() asm volatile("cp.async.commit_group;" ::: "memory")
#define CP_WAIT_ALL() asm volatile("cp.async.wait_group 0;" ::: "memory")

__device__ __forceinline__ void ldm_x4(uint32_t& r0, uint32_t& r1,
                                       uint32_t& r2, uint32_t& r3, uint32_t addr) {
    asm volatile("ldmatrix.sync.aligned.m8n8.x4.shared.b16 {%0,%1,%2,%3}, [%4];"
                 : "=r"(r0), "=r"(r1), "=r"(r2), "=r"(r3) : "r"(addr));
}
__device__ __forceinline__ void mma_bf16(float& d0, float& d1, float& d2, float& d3,
                                         uint32_t a0, uint32_t a1, uint32_t a2, uint32_t a3,
                                         uint32_t b0, uint32_t b1) {
    asm volatile("mma.sync.aligned.m16n8k16.row.col.f32.bf16.bf16.f32 "
                 "{%0,%1,%2,%3}, {%4,%5,%6,%7}, {%8,%9}, {%0,%1,%2,%3};"
                 : "+f"(d0), "+f"(d1), "+f"(d2), "+f"(d3)
                 : "r"(a0), "r"(a1), "r"(a2), "r"(a3), "r"(b0), "r"(b1));
}

// ---------------------------------------------------------------------------
// fp32 -> (hi, lo) bf16 split, vectorized x4
// ---------------------------------------------------------------------------
__global__ __launch_bounds__(256) void cvt_hilo_kernel(
    const float* __restrict__ src, __nv_bfloat16* __restrict__ hi,
    __nv_bfloat16* __restrict__ lo, int n4)
{
    int i = blockIdx.x * 256 + threadIdx.x;
    if (i >= n4) return;
    float4 v = ((const float4*)src)[i];
    __nv_bfloat162 h0, h1, l0, l1;
    h0.x = __float2bfloat16(v.x); h0.y = __float2bfloat16(v.y);
    h1.x = __float2bfloat16(v.z); h1.y = __float2bfloat16(v.w);
    l0.x = __float2bfloat16(v.x - __bfloat162float(h0.x));
    l0.y = __float2bfloat16(v.y - __bfloat162float(h0.y));
    l1.x = __float2bfloat16(v.z - __bfloat162float(h1.x));
    l1.y = __float2bfloat16(v.w - __bfloat162float(h1.y));
    ((__nv_bfloat162*)hi)[i * 2 + 0] = h0;
    ((__nv_bfloat162*)hi)[i * 2 + 1] = h1;
    ((__nv_bfloat162*)lo)[i * 2 + 0] = l0;
    ((__nv_bfloat162*)lo)[i * 2 + 1] = l1;
}

// ---------------------------------------------------------------------------
// mma.sync GEMM: Y[m,n] = sum_k X[m,k]*W[n,k] + bias[n], hi/lo bf16 3-pass.
// CTA tile M=128, N=128, BK=32. 8 warps, warp tile 32x64 (2x8 m16n8k16).
// cp.async double-buffered smem; rows padded to 80 B for conflict-free ldmatrix.
// ---------------------------------------------------------------------------
#define ROWB 80                       // 32 bf16 = 64 B data + 16 B pad
#define TILEB (128 * ROWB)            // 10240 B per tile
#define OFF_AHI 0
#define OFF_ALO (1 * TILEB)
#define OFF_BHI (2 * TILEB)
#define OFF_BLO (3 * TILEB)
#define STAGEB  (4 * TILEB)           // 40960 B per stage
#define GEMM_SMEM (2 * STAGEB)        // 81920 B
#define KITERS (CD / 32)              // 32

__global__ __launch_bounds__(256) void gemm_mma_kernel(
    const __nv_bfloat16* __restrict__ Ahi, const __nv_bfloat16* __restrict__ Alo,
    const __nv_bfloat16* __restrict__ Bhi, const __nv_bfloat16* __restrict__ Blo,
    const float* __restrict__ bias, float* __restrict__ Y, int qkv_layout)
{
    extern __shared__ char smem[];
    const uint32_t sbase = smem_to_u32(smem);
    const int tid  = threadIdx.x;
    const int wid  = tid >> 5;
    const int lane = tid & 31;
    const int n0 = blockIdx.x * 128;
    const int m0 = blockIdx.y * 128;
    const int warp_m = wid >> 1;          // 0..3 -> rows 32*warp_m
    const int warp_n = wid & 1;           // 0..1 -> cols 64*warp_n

    // loader slots: per tile 512 uint4 (128 rows x 4 chunks); 2 per thread
    const int s0r = tid >> 2,           s0c = tid & 3;
    const int s1r = (tid + 256) >> 2,   s1c = (tid + 256) & 3;

    const uint4* gA_hi = (const uint4*)Ahi;
    const uint4* gA_lo = (const uint4*)Alo;
    const uint4* gB_hi = (const uint4*)Bhi;
    const uint4* gB_lo = (const uint4*)Blo;
    const int grow = CD / 8;              // uint4 per gmem row

    auto prefetch = [&](int it, int stage) {
        const int kv4 = it * 4;           // uint4 offset within row
        const uint32_t sb = sbase + stage * STAGEB;
        uint32_t sa0 = sb + (uint32_t)(s0r * ROWB + s0c * 16);
        uint32_t sa1 = sb + (uint32_t)(s1r * ROWB + s1c * 16);
        size_t ga0 = (size_t)(m0 + s0r) * grow + kv4 + s0c;
        size_t ga1 = (size_t)(m0 + s1r) * grow + kv4 + s1c;
        size_t gb0 = (size_t)(n0 + s0r) * grow + kv4 + s0c;
        size_t gb1 = (size_t)(n0 + s1r) * grow + kv4 + s1c;
        cp16(sa0 + OFF_AHI, gA_hi + ga0);  cp16(sa1 + OFF_AHI, gA_hi + ga1);
        cp16(sa0 + OFF_ALO, gA_lo + ga0);  cp16(sa1 + OFF_ALO, gA_lo + ga1);
        cp16(sa0 + OFF_BHI, gB_hi + gb0);  cp16(sa1 + OFF_BHI, gB_hi + gb1);
        cp16(sa0 + OFF_BLO, gB_lo + gb0);  cp16(sa1 + OFF_BLO, gB_lo + gb1);
    };

    float acc[2][8][4];
    #pragma unroll
    for (int i = 0; i < 2; ++i)
        #pragma unroll
        for (int j = 0; j < 8; ++j)
            #pragma unroll
            for (int v = 0; v < 4; ++v) acc[i][j][v] = 0.0f;

    // ldmatrix lane address components (byte offsets within a tile)
    const uint32_t a_row = (uint32_t)(warp_m * 32 + (lane & 15));
    const uint32_t a_col = (uint32_t)((lane >> 4) * 16);
    const uint32_t b_rowbase = (uint32_t)(warp_n * 64 + (lane & 7) + ((lane >> 4) << 3));
    const uint32_t b_col = (uint32_t)(((lane >> 3) & 1) * 16);

    prefetch(0, 0);
    CP_COMMIT();

    for (int it = 0; it < KITERS; ++it) {
        CP_WAIT_ALL();
        __syncthreads();
        if (it + 1 < KITERS) { prefetch(it + 1, (it + 1) & 1); CP_COMMIT(); }

        const uint32_t st = sbase + (it & 1) * STAGEB;
        #pragma unroll
        for (int kh = 0; kh < 2; ++kh) {
            const uint32_t kb = (uint32_t)(kh * 32);
            uint32_t ahi[2][4], alo[2][4];
            #pragma unroll
            for (int mt = 0; mt < 2; ++mt) {
                uint32_t addr = st + (a_row + mt * 16) * ROWB + kb + a_col;
                ldm_x4(ahi[mt][0], ahi[mt][1], ahi[mt][2], ahi[mt][3], addr + OFF_AHI);
                ldm_x4(alo[mt][0], alo[mt][1], alo[mt][2], alo[mt][3], addr + OFF_ALO);
            }
            uint32_t bhi[8][2], blo[8][2];
            #pragma unroll
            for (int ng = 0; ng < 4; ++ng) {      // 2 n8-tiles per ldmatrix.x4
                uint32_t addr = st + (b_rowbase + ng * 16) * ROWB + kb + b_col;
                ldm_x4(bhi[2 * ng][0], bhi[2 * ng][1], bhi[2 * ng + 1][0],
                       bhi[2 * ng + 1][1], addr + OFF_BHI);
                ldm_x4(blo[2 * ng][0], blo[2 * ng][1], blo[2 * ng + 1][0],
                       blo[2 * ng + 1][1], addr + OFF_BLO);
            }
            #pragma unroll
            for (int mt = 0; mt < 2; ++mt)
                #pragma unroll
                for (int nt = 0; nt < 8; ++nt) {
                    float* d = acc[mt][nt];
                    mma_bf16(d[0], d[1], d[2], d[3],
                             ahi[mt][0], ahi[mt][1], ahi[mt][2], ahi[mt][3],
                             bhi[nt][0], bhi[nt][1]);
                    mma_bf16(d[0], d[1], d[2], d[3],
                             ahi[mt][0], ahi[mt][1], ahi[mt][2], ahi[mt][3],
                             blo[nt][0], blo[nt][1]);
                    mma_bf16(d[0], d[1], d[2], d[3],
                             alo[mt][0], alo[mt][1], alo[mt][2], alo[mt][3],
                             bhi[nt][0], bhi[nt][1]);
                }
        }
        __syncthreads();
    }

    // Epilogue: d0,d1 -> row (lane/4), cols 2*(lane%4)+{0,1}; d2,d3 -> row+8
    const int ncolbase = n0 + warp_n * 64;
    const int h  = ncolbase >> 6;         // head (64-aligned per warp)
    #pragma unroll
    for (int mt = 0; mt < 2; ++mt) {
        #pragma unroll
        for (int half = 0; half < 2; ++half) {
            int m = m0 + warp_m * 32 + mt * 16 + (lane >> 2) + half * 8;
            float* dst;
            if (qkv_layout) {
                int bi = m >> 10, tt = m & 1023;
                dst = Y + ((size_t)(bi * CH + h) * CT + tt) * CDK;
            } else {
                dst = Y + (size_t)m * CD + ncolbase;
            }
            #pragma unroll
            for (int nt = 0; nt < 8; ++nt) {
                int c = nt * 8 + (lane & 3) * 2;       // 0..63 within warp cols
                float2 o;
                o.x = acc[mt][nt][half * 2 + 0] + bias[ncolbase + c + 0];
                o.y = acc[mt][nt][half * 2 + 1] + bias[ncolbase + c + 1];
                *(float2*)(dst + c) = o;
            }
        }
    }
}

// ----------------------------------------------------------------------------
// Flash-style causal attention with spatial-distance bias (unchanged, fp32).
// ----------------------------------------------------------------------------
#define QS_STRIDE 68
#define ATTN_SMEM ((2 * 64 * QS_STRIDE + 64 * 64 + 3 * 64) * (int)sizeof(float))

__global__ __launch_bounds__(256) void attn_kernel(
    const float* __restrict__ dist, const float* __restrict__ swp,
    const float* __restrict__ Q, const float* __restrict__ K,
    const float* __restrict__ V, float* __restrict__ Aout)
{
    extern __shared__ float sm[];
    float* Qs   = sm;
    float* KVs  = sm + 64 * QS_STRIDE;
    float* S    = sm + 2 * 64 * QS_STRIDE;
    float* mrow = S + 64 * 64;
    float* lrow = mrow + 64;
    float* crow = lrow + 64;

    const int tx = threadIdx.x, ty = threadIdx.y;
    const int tid = ty * 16 + tx;
    const int qt = blockIdx.x;
    const int bh = blockIdx.y;
    const int b  = bh >> 4;
    const int h  = bh & 15;
    const int qbase = qt * 64;
    const float alphaAbs = fabsf(swp[0]);

    const float* Qp = Q + ((size_t)bh * CT + qbase) * CDK;
    #pragma unroll
    for (int it = 0; it < 4; ++it) {
        int idx = tid + it * 256;
        int r = idx >> 4, d4 = idx & 15;
        *(float4*)(Qs + r * QS_STRIDE + d4 * 4) =
            *(const float4*)(Qp + r * CDK + d4 * 4);
    }
    if (tid < 64) { mrow[tid] = -1e30f; lrow[tid] = 0.0f; }

    float acc_o[4][4] = {};
    __syncthreads();

    for (int jt = 0; jt <= qt; ++jt) {
        const int kbase = jt * 64;

        const float* Kp = K + ((size_t)bh * CT + kbase) * CDK;
        #pragma unroll
        for (int it = 0; it < 4; ++it) {
            int idx = tid + it * 256;
            int r = idx >> 4, d4 = idx & 15;
            *(float4*)(KVs + r * QS_STRIDE + d4 * 4) =
                *(const float4*)(Kp + r * CDK + d4 * 4);
        }
        __syncthreads();

        float accs[4][4] = {};
        #pragma unroll
        for (int d4 = 0; d4 < 16; ++d4) {
            float4 a[4], bb[4];
            #pragma unroll
            for (int i = 0; i < 4; ++i)
                a[i] = *(const float4*)(Qs + (ty + i * 16) * QS_STRIDE + d4 * 4);
            #pragma unroll
            for (int j = 0; j < 4; ++j)
                bb[j] = *(const float4*)(KVs + (tx + j * 16) * QS_STRIDE + d4 * 4);
            #pragma unroll
            for (int i = 0; i < 4; ++i)
                #pragma unroll
                for (int j = 0; j < 4; ++j)
                    accs[i][j] += a[i].x * bb[j].x + a[i].y * bb[j].y
                                + a[i].z * bb[j].z + a[i].w * bb[j].w;
        }

        const bool diag = (jt == qt);
        #pragma unroll
        for (int i = 0; i < 4; ++i) {
            int qg = qbase + ty + i * 16;
            const float* drow = dist + ((size_t)b * CT + qg) * CT + kbase;
            #pragma unroll
            for (int j = 0; j < 4; ++j) {
                int c = tx + j * 16;
                float s = accs[i][j] * 0.125f - alphaAbs * drow[c];
                if (diag && (kbase + c) > qg) s = -1e30f;
                S[(ty + i * 16) * 64 + c] = s;
            }
        }
        __syncthreads();

        const float* Vp = V + ((size_t)bh * CT + kbase) * CDK;
        #pragma unroll
        for (int it = 0; it < 4; ++it) {
            int idx = tid + it * 256;
            int r = idx >> 4, d4 = idx & 15;
            *(float4*)(KVs + r * QS_STRIDE + d4 * 4) =
                *(const float4*)(Vp + r * CDK + d4 * 4);
        }
        {
            int w = tid >> 5, lane = tid & 31;
            #pragma unroll
            for (int rr = 0; rr < 8; ++rr) {
                int r = w * 8 + rr;
                float s0 = S[r * 64 + lane];
                float s1 = S[r * 64 + 32 + lane];
                float mx = fmaxf(s0, s1);
                #pragma unroll
                for (int off = 16; off > 0; off >>= 1)
                    mx = fmaxf(mx, __shfl_xor_sync(0xffffffffu, mx, off));
                float mold = mrow[r];
                float mnew = fmaxf(mold, mx);
                float p0 = __expf(s0 - mnew);
                float p1 = __expf(s1 - mnew);
                float sum = p0 + p1;
                #pragma unroll
                for (int off = 16; off > 0; off >>= 1)
                    sum += __shfl_xor_sync(0xffffffffu, sum, off);
                S[r * 64 + lane] = p0;
                S[r * 64 + 32 + lane] = p1;
                if (lane == 0) {
                    float corr = __expf(mold - mnew);
                    crow[r] = corr;
                    lrow[r] = lrow[r] * corr + sum;
                    mrow[r] = mnew;
                }
            }
        }
        __syncthreads();

        float ci[4];
        #pragma unroll
        for (int i = 0; i < 4; ++i) ci[i] = crow[ty + i * 16];
        #pragma unroll
        for (int i = 0; i < 4; ++i)
            #pragma unroll
            for (int j = 0; j < 4; ++j) acc_o[i][j] *= ci[i];
        #pragma unroll
        for (int c = 0; c < 64; ++c) {
            float p[4], v[4];
            #pragma unroll
            for (int i = 0; i < 4; ++i) p[i] = S[(ty + i * 16) * 64 + c];
            #pragma unroll
            for (int j = 0; j < 4; ++j) v[j] = KVs[c * QS_STRIDE + tx + j * 16];
            #pragma unroll
            for (int i = 0; i < 4; ++i)
                #pragma unroll
                for (int j = 0; j < 4; ++j) acc_o[i][j] += p[i] * v[j];
        }
        __syncthreads();
    }

    float linv[4];
    #pragma unroll
    for (int i = 0; i < 4; ++i) linv[i] = 1.0f / lrow[ty + i * 16];
    #pragma unroll
    for (int i = 0; i < 4; ++i) {
        int t = qbase + ty + i * 16;
        float* dst = Aout + ((size_t)b * CT + t) * CD + h * CDK;
        #pragma unroll
        for (int j = 0; j < 4; ++j)
            dst[tx + j * 16] = acc_o[i][j] * linv[i];
    }
}

// ----------------------------------------------------------------------------
// Launch
// Inputs: x, s2_distances, mask, Wq, bq, Wk, bk, Wv, bv, Wo, bo, spatial_weight
// ----------------------------------------------------------------------------
extern "C" void kernel_launch(void* const* d_in, const int* in_sizes, int n_in,
                              void* d_out, int out_size)
{
    (void)in_sizes; (void)n_in; (void)out_size;
    const float* x    = (const float*)d_in[0];
    const float* dist = (const float*)d_in[1];
    const float* Wq = (const float*)d_in[3];
    const float* bq = (const float*)d_in[4];
    const float* Wk = (const float*)d_in[5];
    const float* bk = (const float*)d_in[6];
    const float* Wv = (const float*)d_in[7];
    const float* bv = (const float*)d_in[8];
    const float* Wo = (const float*)d_in[9];
    const float* bo = (const float*)d_in[10];
    const float* sw = (const float*)d_in[11];

    float *pQ, *pK, *pV, *pA;
    __nv_bfloat16 *pXhi, *pXlo, *pWhi, *pWlo;
    cudaGetSymbolAddress((void**)&pQ, g_Q);
    cudaGetSymbolAddress((void**)&pK, g_K);
    cudaGetSymbolAddress((void**)&pV, g_V);
    cudaGetSymbolAddress((void**)&pA, g_A);
    cudaGetSymbolAddress((void**)&pXhi, g_Xhi);
    cudaGetSymbolAddress((void**)&pXlo, g_Xlo);
    cudaGetSymbolAddress((void**)&pWhi, g_Whi);
    cudaGetSymbolAddress((void**)&pWlo, g_Wlo);

    cudaFuncSetAttribute(gemm_mma_kernel,
                         cudaFuncAttributeMaxDynamicSharedMemorySize, GEMM_SMEM);
    cudaFuncSetAttribute(attn_kernel,
                         cudaFuncAttributeMaxDynamicSharedMemorySize, ATTN_SMEM);

    const int nX4 = CM * CD / 4;          // 1M float4
    const int nW4 = CD * CD / 4;          // 256K float4
    dim3 gg(CD / 128, CM / 128);          // (8, 32)

    cvt_hilo_kernel<<<nX4 / 256, 256>>>(x, pXhi, pXlo, nX4);

    cvt_hilo_kernel<<<nW4 / 256, 256>>>(Wq, pWhi, pWlo, nW4);
    gemm_mma_kernel<<<gg, 256, GEMM_SMEM>>>(pXhi, pXlo, pWhi, pWlo, bq, pQ, 1);
    cvt_hilo_kernel<<<nW4 / 256, 256>>>(Wk, pWhi, pWlo, nW4);
    gemm_mma_kernel<<<gg, 256, GEMM_SMEM>>>(pXhi, pXlo, pWhi, pWlo, bk, pK, 1);
    cvt_hilo_kernel<<<nW4 / 256, 256>>>(Wv, pWhi, pWlo, nW4);
    gemm_mma_kernel<<<gg, 256, GEMM_SMEM>>>(pXhi, pXlo, pWhi, pWlo, bv, pV, 1);

    attn_kernel<<<dim3(CT / 64, CB * CH), dim3(16, 16), ATTN_SMEM>>>(
        dist, sw, pQ, pK, pV, pA);

    cvt_hilo_kernel<<<nX4 / 256, 256>>>(pA, pXhi, pXlo, nX4);
    cvt_hilo_kernel<<<nW4 / 256, 256>>>(Wo, pWhi, pWlo, nW4);
    gemm_mma_kernel<<<gg, 256, GEMM_SMEM>>>(pXhi, pXlo, pWhi, pWlo, bo,
                                            (float*)d_out, 0);
}

// round 13
// speedup vs baseline: 2.7226x; 1.5516x over previous
#include <cuda_runtime.h>
#include <cuda_bf16.h>
#include <math.h>
#include <cstdint>

// Problem constants
#define CB 4
#define CT 1024
#define CD 1024
#define CH 16
#define CDK 64
#define CM (CB * CT)   // 4096 rows

// ---------------------------------------------------------------------------
// Scratch (device globals: allocation-free)
// ---------------------------------------------------------------------------
__device__ __align__(16) __nv_bfloat16 g_Qhi[CB * CH * CT * CDK];
__device__ __align__(16) __nv_bfloat16 g_Qlo[CB * CH * CT * CDK];
__device__ __align__(16) __nv_bfloat16 g_Khi[CB * CH * CT * CDK];
__device__ __align__(16) __nv_bfloat16 g_Klo[CB * CH * CT * CDK];
__device__ __align__(16) __nv_bfloat16 g_Vhi[CB * CH * CT * CDK];
__device__ __align__(16) __nv_bfloat16 g_Vlo[CB * CH * CT * CDK];
__device__ __align__(16) float g_A[CB * CT * CD];         // attention out [B,T,D]
__device__ __align__(16) __nv_bfloat16 g_Xhi[CM * CD];    // activations hi/lo
__device__ __align__(16) __nv_bfloat16 g_Xlo[CM * CD];
__device__ __align__(16) __nv_bfloat16 g_Whi[CD * CD];    // current weight hi/lo
__device__ __align__(16) __nv_bfloat16 g_Wlo[CD * CD];

// ---------------------------------------------------------------------------
// Baseline-PTX helpers (all legal at compute_103: no arch-'a' features)
// ---------------------------------------------------------------------------
__device__ __forceinline__ uint32_t smem_to_u32(const void* p) {
    uint32_t a;
    asm("{ .reg .u64 t; cvta.to.shared.u64 t, %1; cvt.u32.u64 %0, t; }"
        : "=r"(a) : "l"(p));
    return a;
}
__device__ __forceinline__ void cp16(uint32_t saddr, const void* gptr) {
    asm volatile("cp.async.cg.shared.global [%0], [%1], 16;"
                 :: "r"(saddr), "l"(gptr));
}
#define CP_COMMIT() asm volatile("cp.async.commit_group;" ::: "memory")
#define CP_WAIT_ALL() asm volatile("cp.async.wait_group 0;" ::: "memory")

__device__ __forceinline__ void ldm_x4(uint32_t& r0, uint32_t& r1,
                                       uint32_t& r2, uint32_t& r3, uint32_t addr) {
    asm volatile("ldmatrix.sync.aligned.m8n8.x4.shared.b16 {%0,%1,%2,%3}, [%4];"
                 : "=r"(r0), "=r"(r1), "=r"(r2), "=r"(r3) : "r"(addr));
}
__device__ __forceinline__ void ldm_x4t(uint32_t& r0, uint32_t& r1,
                                        uint32_t& r2, uint32_t& r3, uint32_t addr) {
    asm volatile("ldmatrix.sync.aligned.m8n8.x4.trans.shared.b16 {%0,%1,%2,%3}, [%4];"
                 : "=r"(r0), "=r"(r1), "=r"(r2), "=r"(r3) : "r"(addr));
}
__device__ __forceinline__ void mma_bf16(float& d0, float& d1, float& d2, float& d3,
                                         uint32_t a0, uint32_t a1, uint32_t a2, uint32_t a3,
                                         uint32_t b0, uint32_t b1) {
    asm volatile("mma.sync.aligned.m16n8k16.row.col.f32.bf16.bf16.f32 "
                 "{%0,%1,%2,%3}, {%4,%5,%6,%7}, {%8,%9}, {%0,%1,%2,%3};"
                 : "+f"(d0), "+f"(d1), "+f"(d2), "+f"(d3)
                 : "r"(a0), "r"(a1), "r"(a2), "r"(a3), "r"(b0), "r"(b1));
}
// pack two floats into bf16x2 hi, return lo residual pack
__device__ __forceinline__ uint32_t pk_hilo(float x, float y, uint32_t& lo) {
    __nv_bfloat162 h, l;
    h.x = __float2bfloat16(x); h.y = __float2bfloat16(y);
    l.x = __float2bfloat16(x - __bfloat162float(h.x));
    l.y = __float2bfloat16(y - __bfloat162float(h.y));
    lo = *(uint32_t*)&l;
    return *(uint32_t*)&h;
}

// ---------------------------------------------------------------------------
// fp32 -> (hi, lo) bf16 split, vectorized x4
// ---------------------------------------------------------------------------
__global__ __launch_bounds__(256) void cvt_hilo_kernel(
    const float* __restrict__ src, __nv_bfloat16* __restrict__ hi,
    __nv_bfloat16* __restrict__ lo, int n4)
{
    int i = blockIdx.x * 256 + threadIdx.x;
    if (i >= n4) return;
    float4 v = ((const float4*)src)[i];
    __nv_bfloat162 h0, h1, l0, l1;
    h0.x = __float2bfloat16(v.x); h0.y = __float2bfloat16(v.y);
    h1.x = __float2bfloat16(v.z); h1.y = __float2bfloat16(v.w);
    l0.x = __float2bfloat16(v.x - __bfloat162float(h0.x));
    l0.y = __float2bfloat16(v.y - __bfloat162float(h0.y));
    l1.x = __float2bfloat16(v.z - __bfloat162float(h1.x));
    l1.y = __float2bfloat16(v.w - __bfloat162float(h1.y));
    ((__nv_bfloat162*)hi)[i * 2 + 0] = h0;
    ((__nv_bfloat162*)hi)[i * 2 + 1] = h1;
    ((__nv_bfloat162*)lo)[i * 2 + 0] = l0;
    ((__nv_bfloat162*)lo)[i * 2 + 1] = l1;
}

// ---------------------------------------------------------------------------
// mma.sync GEMM: Y[m,n] = sum_k X[m,k]*W[n,k] + bias[n], hi/lo bf16 3-pass.
// CTA tile M=128, N=128, BK=32. 8 warps, warp tile 32x64 (2x8 m16n8k16).
// qkv_layout==1: write bf16 hi/lo pair in [B,H,T,DK]; else fp32 [M,N].
// ---------------------------------------------------------------------------
#define ROWB 80                       // 32 bf16 = 64 B data + 16 B pad
#define TILEB (128 * ROWB)            // 10240 B per tile
#define OFF_AHI 0
#define OFF_ALO (1 * TILEB)
#define OFF_BHI (2 * TILEB)
#define OFF_BLO (3 * TILEB)
#define STAGEB  (4 * TILEB)           // 40960 B per stage
#define GEMM_SMEM (2 * STAGEB)        // 81920 B
#define KITERS (CD / 32)              // 32

__global__ __launch_bounds__(256) void gemm_mma_kernel(
    const __nv_bfloat16* __restrict__ Ahi, const __nv_bfloat16* __restrict__ Alo,
    const __nv_bfloat16* __restrict__ Bhi, const __nv_bfloat16* __restrict__ Blo,
    const float* __restrict__ bias, float* __restrict__ Y,
    __nv_bfloat16* __restrict__ Yhi, __nv_bfloat16* __restrict__ Ylo,
    int qkv_layout)
{
    extern __shared__ char smem[];
    const uint32_t sbase = smem_to_u32(smem);
    const int tid  = threadIdx.x;
    const int wid  = tid >> 5;
    const int lane = tid & 31;
    const int n0 = blockIdx.x * 128;
    const int m0 = blockIdx.y * 128;
    const int warp_m = wid >> 1;
    const int warp_n = wid & 1;

    const int s0r = tid >> 2,           s0c = tid & 3;
    const int s1r = (tid + 256) >> 2,   s1c = (tid + 256) & 3;

    const uint4* gA_hi = (const uint4*)Ahi;
    const uint4* gA_lo = (const uint4*)Alo;
    const uint4* gB_hi = (const uint4*)Bhi;
    const uint4* gB_lo = (const uint4*)Blo;
    const int grow = CD / 8;

    auto prefetch = [&](int it, int stage) {
        const int kv4 = it * 4;
        const uint32_t sb = sbase + stage * STAGEB;
        uint32_t sa0 = sb + (uint32_t)(s0r * ROWB + s0c * 16);
        uint32_t sa1 = sb + (uint32_t)(s1r * ROWB + s1c * 16);
        size_t ga0 = (size_t)(m0 + s0r) * grow + kv4 + s0c;
        size_t ga1 = (size_t)(m0 + s1r) * grow + kv4 + s1c;
        size_t gb0 = (size_t)(n0 + s0r) * grow + kv4 + s0c;
        size_t gb1 = (size_t)(n0 + s1r) * grow + kv4 + s1c;
        cp16(sa0 + OFF_AHI, gA_hi + ga0);  cp16(sa1 + OFF_AHI, gA_hi + ga1);
        cp16(sa0 + OFF_ALO, gA_lo + ga0);  cp16(sa1 + OFF_ALO, gA_lo + ga1);
        cp16(sa0 + OFF_BHI, gB_hi + gb0);  cp16(sa1 + OFF_BHI, gB_hi + gb1);
        cp16(sa0 + OFF_BLO, gB_lo + gb0);  cp16(sa1 + OFF_BLO, gB_lo + gb1);
    };

    float acc[2][8][4];
    #pragma unroll
    for (int i = 0; i < 2; ++i)
        #pragma unroll
        for (int j = 0; j < 8; ++j)
            #pragma unroll
            for (int v = 0; v < 4; ++v) acc[i][j][v] = 0.0f;

    const uint32_t a_row = (uint32_t)(warp_m * 32 + (lane & 15));
    const uint32_t a_col = (uint32_t)((lane >> 4) * 16);
    const uint32_t b_rowbase = (uint32_t)(warp_n * 64 + (lane & 7) + ((lane >> 4) << 3));
    const uint32_t b_col = (uint32_t)(((lane >> 3) & 1) * 16);

    prefetch(0, 0);
    CP_COMMIT();

    for (int it = 0; it < KITERS; ++it) {
        CP_WAIT_ALL();
        __syncthreads();
        if (it + 1 < KITERS) { prefetch(it + 1, (it + 1) & 1); CP_COMMIT(); }

        const uint32_t st = sbase + (it & 1) * STAGEB;
        #pragma unroll
        for (int kh = 0; kh < 2; ++kh) {
            const uint32_t kb = (uint32_t)(kh * 32);
            uint32_t ahi[2][4], alo[2][4];
            #pragma unroll
            for (int mt = 0; mt < 2; ++mt) {
                uint32_t addr = st + (a_row + mt * 16) * ROWB + kb + a_col;
                ldm_x4(ahi[mt][0], ahi[mt][1], ahi[mt][2], ahi[mt][3], addr + OFF_AHI);
                ldm_x4(alo[mt][0], alo[mt][1], alo[mt][2], alo[mt][3], addr + OFF_ALO);
            }
            uint32_t bhi[8][2], blo[8][2];
            #pragma unroll
            for (int ng = 0; ng < 4; ++ng) {
                uint32_t addr = st + (b_rowbase + ng * 16) * ROWB + kb + b_col;
                ldm_x4(bhi[2 * ng][0], bhi[2 * ng][1], bhi[2 * ng + 1][0],
                       bhi[2 * ng + 1][1], addr + OFF_BHI);
                ldm_x4(blo[2 * ng][0], blo[2 * ng][1], blo[2 * ng + 1][0],
                       blo[2 * ng + 1][1], addr + OFF_BLO);
            }
            #pragma unroll
            for (int mt = 0; mt < 2; ++mt)
                #pragma unroll
                for (int nt = 0; nt < 8; ++nt) {
                    float* d = acc[mt][nt];
                    mma_bf16(d[0], d[1], d[2], d[3],
                             ahi[mt][0], ahi[mt][1], ahi[mt][2], ahi[mt][3],
                             bhi[nt][0], bhi[nt][1]);
                    mma_bf16(d[0], d[1], d[2], d[3],
                             ahi[mt][0], ahi[mt][1], ahi[mt][2], ahi[mt][3],
                             blo[nt][0], blo[nt][1]);
                    mma_bf16(d[0], d[1], d[2], d[3],
                             alo[mt][0], alo[mt][1], alo[mt][2], alo[mt][3],
                             bhi[nt][0], bhi[nt][1]);
                }
        }
        __syncthreads();
    }

    // Epilogue
    const int ncolbase = n0 + warp_n * 64;
    const int h  = ncolbase >> 6;
    #pragma unroll
    for (int mt = 0; mt < 2; ++mt) {
        #pragma unroll
        for (int half = 0; half < 2; ++half) {
            int m = m0 + warp_m * 32 + mt * 16 + (lane >> 2) + half * 8;
            if (qkv_layout) {
                int bi = m >> 10, tt = m & 1023;
                size_t base = ((size_t)(bi * CH + h) * CT + tt) * CDK;
                #pragma unroll
                for (int nt = 0; nt < 8; ++nt) {
                    int c = nt * 8 + (lane & 3) * 2;
                    float y0 = acc[mt][nt][half * 2 + 0] + bias[ncolbase + c + 0];
                    float y1 = acc[mt][nt][half * 2 + 1] + bias[ncolbase + c + 1];
                    uint32_t lo, hi = pk_hilo(y0, y1, lo);
                    *(uint32_t*)(Yhi + base + c) = hi;
                    *(uint32_t*)(Ylo + base + c) = lo;
                }
            } else {
                float* dst = Y + (size_t)m * CD + ncolbase;
                #pragma unroll
                for (int nt = 0; nt < 8; ++nt) {
                    int c = nt * 8 + (lane & 3) * 2;
                    float2 o;
                    o.x = acc[mt][nt][half * 2 + 0] + bias[ncolbase + c + 0];
                    o.y = acc[mt][nt][half * 2 + 1] + bias[ncolbase + c + 1];
                    *(float2*)(dst + c) = o;
                }
            }
        }
    }
}

// ----------------------------------------------------------------------------
// mma.sync flash attention, hi/lo bf16 3-pass for QK^T and PV.
// Br=Bc=64, 4 warps (128 thr); warp w owns rows w*16..w*16+15 (all 64 cols).
// Attention tiles are 64x64 bf16 = 128 B/row -> AROWB=144 (128 data + 16 pad).
// cp.async double-buffered K/V hi/lo tiles. Causal; spatial bias from gmem.
// ----------------------------------------------------------------------------
#define AROWB 144                     // 64 bf16 = 128 B data + 16 B pad
#define ATILEB (64 * AROWB)           // 9216
#define ASM_QHI 0
#define ASM_QLO ATILEB
#define ASM_KV  (2 * ATILEB)          // 18432
#define AST_KHI 0
#define AST_KLO (1 * ATILEB)
#define AST_VHI (2 * ATILEB)
#define AST_VLO (3 * ATILEB)
#define ASTAGEB (4 * ATILEB)          // 36864
#define ATTN_SMEM (2 * ATILEB + 2 * ASTAGEB)   // 92160

__global__ __launch_bounds__(128) void attn_mma_kernel(
    const float* __restrict__ dist, const float* __restrict__ swp,
    const __nv_bfloat16* __restrict__ Qhi, const __nv_bfloat16* __restrict__ Qlo,
    const __nv_bfloat16* __restrict__ Khi, const __nv_bfloat16* __restrict__ Klo,
    const __nv_bfloat16* __restrict__ Vhi, const __nv_bfloat16* __restrict__ Vlo,
    float* __restrict__ Aout)
{
    extern __shared__ char smem[];
    const uint32_t sbase = smem_to_u32(smem);
    const int tid  = threadIdx.x;
    const int wid  = tid >> 5;
    const int lane = tid & 31;
    const int qt = blockIdx.x;
    const int bh = blockIdx.y;
    const int b  = bh >> 4;
    const int h  = bh & 15;
    const int qbase = qt * 64;
    const float alpha = fabsf(swp[0]);

    auto prefetch_kv = [&](int jt, int stage) {
        const uint32_t sb = sbase + ASM_KV + stage * ASTAGEB;
        const int kb = jt * 64;
        #pragma unroll
        for (int i = 0; i < 4; ++i) {
            int slot = tid + i * 128;         // 0..511
            int row = slot >> 3, c16 = slot & 7;
            uint32_t sa = sb + (uint32_t)(row * AROWB + c16 * 16);
            size_t g = ((size_t)bh * CT + kb + row) * (CDK / 8) + c16;
            cp16(sa + AST_KHI, (const uint4*)Khi + g);
            cp16(sa + AST_KLO, (const uint4*)Klo + g);
            cp16(sa + AST_VHI, (const uint4*)Vhi + g);
            cp16(sa + AST_VLO, (const uint4*)Vlo + g);
        }
    };

    // Q tile load + first KV stage
    #pragma unroll
    for (int i = 0; i < 4; ++i) {
        int slot = tid + i * 128;
        int row = slot >> 3, c16 = slot & 7;
        uint32_t sa = sbase + (uint32_t)(row * AROWB + c16 * 16);
        size_t g = ((size_t)bh * CT + qbase + row) * (CDK / 8) + c16;
        cp16(sa + ASM_QHI, (const uint4*)Qhi + g);
        cp16(sa + ASM_QLO, (const uint4*)Qlo + g);
    }
    prefetch_kv(0, 0);
    CP_COMMIT();

    // fragment address components
    const uint32_t a_row = (uint32_t)(wid * 16 + (lane & 15));
    const uint32_t a_col = (uint32_t)((lane >> 4) * 16);
    const uint32_t b_rowbase = (uint32_t)((lane & 7) + ((lane >> 4) << 3));
    const uint32_t b_col = (uint32_t)(((lane >> 3) & 1) * 16);
    const uint32_t v_row = (uint32_t)(lane & 15);
    const uint32_t v_col = (uint32_t)((lane >> 4) * 16);

    uint32_t qhi[4][4], qlo[4][4];
    float oacc[8][4];
    #pragma unroll
    for (int nt = 0; nt < 8; ++nt)
        #pragma unroll
        for (int v = 0; v < 4; ++v) oacc[nt][v] = 0.0f;
    float m0 = -1e30f, m1 = -1e30f, l0 = 0.0f, l1 = 0.0f;

    const int r0 = lane >> 2;
    const int cbase = (lane & 3) * 2;
    const int row0g = qbase + wid * 16 + r0;
    const float* distrow0 = dist + ((size_t)b * CT + row0g) * CT;
    const float* distrow1 = distrow0 + 8 * CT;

    for (int jt = 0; jt <= qt; ++jt) {
        CP_WAIT_ALL();
        __syncthreads();
        if (jt == 0) {
            #pragma unroll
            for (int ks = 0; ks < 4; ++ks) {
                uint32_t addr = sbase + a_row * AROWB + ks * 32 + a_col;
                ldm_x4(qhi[ks][0], qhi[ks][1], qhi[ks][2], qhi[ks][3], addr + ASM_QHI);
                ldm_x4(qlo[ks][0], qlo[ks][1], qlo[ks][2], qlo[ks][3], addr + ASM_QLO);
            }
        }
        if (jt + 1 <= qt) { prefetch_kv(jt + 1, (jt + 1) & 1); CP_COMMIT(); }

        const uint32_t st = sbase + ASM_KV + (jt & 1) * ASTAGEB;

        // ---- S = Q K^T (hi/lo 3-pass) ----
        float sacc[8][4];
        #pragma unroll
        for (int nt = 0; nt < 8; ++nt)
            #pragma unroll
            for (int v = 0; v < 4; ++v) sacc[nt][v] = 0.0f;

        #pragma unroll
        for (int ks = 0; ks < 4; ++ks) {
            uint32_t kh[8][2], kl[8][2];
            #pragma unroll
            for (int ng = 0; ng < 4; ++ng) {
                uint32_t addr = st + (b_rowbase + ng * 16) * AROWB + ks * 32 + b_col;
                ldm_x4(kh[2 * ng][0], kh[2 * ng][1], kh[2 * ng + 1][0],
                       kh[2 * ng + 1][1], addr + AST_KHI);
                ldm_x4(kl[2 * ng][0], kl[2 * ng][1], kl[2 * ng + 1][0],
                       kl[2 * ng + 1][1], addr + AST_KLO);
            }
            #pragma unroll
            for (int nt = 0; nt < 8; ++nt) {
                float* d = sacc[nt];
                mma_bf16(d[0], d[1], d[2], d[3],
                         qhi[ks][0], qhi[ks][1], qhi[ks][2], qhi[ks][3],
                         kh[nt][0], kh[nt][1]);
                mma_bf16(d[0], d[1], d[2], d[3],
                         qhi[ks][0], qhi[ks][1], qhi[ks][2], qhi[ks][3],
                         kl[nt][0], kl[nt][1]);
                mma_bf16(d[0], d[1], d[2], d[3],
                         qlo[ks][0], qlo[ks][1], qlo[ks][2], qlo[ks][3],
                         kh[nt][0], kh[nt][1]);
            }
        }

        // ---- bias + causal mask + online softmax ----
        const bool diag = (jt == qt);
        const int kbase = jt * 64;
        const int rw0 = wid * 16 + r0;       // within-tile row (diag: qbase==kbase)
        const int rw1 = rw0 + 8;
        float p[8][4];
        float mx0 = -1e30f, mx1 = -1e30f;
        #pragma unroll
        for (int nt = 0; nt < 8; ++nt) {
            int c = nt * 8 + cbase;
            float2 dv0 = *(const float2*)(distrow0 + kbase + c);
            float2 dv1 = *(const float2*)(distrow1 + kbase + c);
            float s0 = sacc[nt][0] * 0.125f - alpha * dv0.x;
            float s1 = sacc[nt][1] * 0.125f - alpha * dv0.y;
            float s2 = sacc[nt][2] * 0.125f - alpha * dv1.x;
            float s3 = sacc[nt][3] * 0.125f - alpha * dv1.y;
            if (diag) {
                if (c     > rw0) s0 = -1e30f;
                if (c + 1 > rw0) s1 = -1e30f;
                if (c     > rw1) s2 = -1e30f;
                if (c + 1 > rw1) s3 = -1e30f;
            }
            p[nt][0] = s0; p[nt][1] = s1; p[nt][2] = s2; p[nt][3] = s3;
            mx0 = fmaxf(mx0, fmaxf(s0, s1));
            mx1 = fmaxf(mx1, fmaxf(s2, s3));
        }
        mx0 = fmaxf(mx0, __shfl_xor_sync(0xffffffffu, mx0, 1));
        mx0 = fmaxf(mx0, __shfl_xor_sync(0xffffffffu, mx0, 2));
        mx1 = fmaxf(mx1, __shfl_xor_sync(0xffffffffu, mx1, 1));
        mx1 = fmaxf(mx1, __shfl_xor_sync(0xffffffffu, mx1, 2));
        float mn0 = fmaxf(m0, mx0), mn1 = fmaxf(m1, mx1);
        float corr0 = __expf(m0 - mn0), corr1 = __expf(m1 - mn1);
        float sum0 = 0.0f, sum1 = 0.0f;
        #pragma unroll
        for (int nt = 0; nt < 8; ++nt) {
            p[nt][0] = __expf(p[nt][0] - mn0);
            p[nt][1] = __expf(p[nt][1] - mn0);
            p[nt][2] = __expf(p[nt][2] - mn1);
            p[nt][3] = __expf(p[nt][3] - mn1);
            sum0 += p[nt][0] + p[nt][1];
            sum1 += p[nt][2] + p[nt][3];
        }
        sum0 += __shfl_xor_sync(0xffffffffu, sum0, 1);
        sum0 += __shfl_xor_sync(0xffffffffu, sum0, 2);
        sum1 += __shfl_xor_sync(0xffffffffu, sum1, 1);
        sum1 += __shfl_xor_sync(0xffffffffu, sum1, 2);
        l0 = l0 * corr0 + sum0;  l1 = l1 * corr1 + sum1;
        m0 = mn0;  m1 = mn1;
        #pragma unroll
        for (int nt = 0; nt < 8; ++nt) {
            oacc[nt][0] *= corr0; oacc[nt][1] *= corr0;
            oacc[nt][2] *= corr1; oacc[nt][3] *= corr1;
        }

        // ---- P -> A fragments (hi/lo), direct from registers ----
        uint32_t pah[4][4], pal[4][4];
        #pragma unroll
        for (int ks = 0; ks < 4; ++ks) {
            pah[ks][0] = pk_hilo(p[2 * ks][0],     p[2 * ks][1],     pal[ks][0]);
            pah[ks][1] = pk_hilo(p[2 * ks][2],     p[2 * ks][3],     pal[ks][1]);
            pah[ks][2] = pk_hilo(p[2 * ks + 1][0], p[2 * ks + 1][1], pal[ks][2]);
            pah[ks][3] = pk_hilo(p[2 * ks + 1][2], p[2 * ks + 1][3], pal[ks][3]);
        }

        // ---- O += P V (hi/lo 3-pass), V via ldmatrix.trans ----
        #pragma unroll
        for (int ks = 0; ks < 4; ++ks) {
            uint32_t vh[8][2], vl[8][2];
            #pragma unroll
            for (int ng = 0; ng < 4; ++ng) {
                uint32_t addr = st + (ks * 16 + v_row) * AROWB + ng * 32 + v_col;
                ldm_x4t(vh[2 * ng][0], vh[2 * ng][1], vh[2 * ng + 1][0],
                        vh[2 * ng + 1][1], addr + AST_VHI);
                ldm_x4t(vl[2 * ng][0], vl[2 * ng][1], vl[2 * ng + 1][0],
                        vl[2 * ng + 1][1], addr + AST_VLO);
            }
            #pragma unroll
            for (int nt = 0; nt < 8; ++nt) {
                float* d = oacc[nt];
                mma_bf16(d[0], d[1], d[2], d[3],
                         pah[ks][0], pah[ks][1], pah[ks][2], pah[ks][3],
                         vh[nt][0], vh[nt][1]);
                mma_bf16(d[0], d[1], d[2], d[3],
                         pal[ks][0], pal[ks][1], pal[ks][2], pal[ks][3],
                         vh[nt][0], vh[nt][1]);
                mma_bf16(d[0], d[1], d[2], d[3],
                         pah[ks][0], pah[ks][1], pah[ks][2], pah[ks][3],
                         vl[nt][0], vl[nt][1]);
            }
        }
        __syncthreads();
    }

    // ---- normalize + write [B,T,D] ----
    const float linv0 = 1.0f / l0, linv1 = 1.0f / l1;
    const int t0 = qbase + wid * 16 + r0;
    float* dst0 = Aout + ((size_t)b * CT + t0) * CD + h * 64;
    float* dst1 = dst0 + (size_t)8 * CD;
    #pragma unroll
    for (int nt = 0; nt < 8; ++nt) {
        int c = nt * 8 + cbase;
        float2 o0, o1;
        o0.x = oacc[nt][0] * linv0; o0.y = oacc[nt][1] * linv0;
        o1.x = oacc[nt][2] * linv1; o1.y = oacc[nt][3] * linv1;
        *(float2*)(dst0 + c) = o0;
        *(float2*)(dst1 + c) = o1;
    }
}

// ----------------------------------------------------------------------------
// Launch
// Inputs: x, s2_distances, mask, Wq, bq, Wk, bk, Wv, bv, Wo, bo, spatial_weight
// ----------------------------------------------------------------------------
extern "C" void kernel_launch(void* const* d_in, const int* in_sizes, int n_in,
                              void* d_out, int out_size)
{
    (void)in_sizes; (void)n_in; (void)out_size;
    const float* x    = (const float*)d_in[0];
    const float* dist = (const float*)d_in[1];
    const float* Wq = (const float*)d_in[3];
    const float* bq = (const float*)d_in[4];
    const float* Wk = (const float*)d_in[5];
    const float* bk = (const float*)d_in[6];
    const float* Wv = (const float*)d_in[7];
    const float* bv = (const float*)d_in[8];
    const float* Wo = (const float*)d_in[9];
    const float* bo = (const float*)d_in[10];
    const float* sw = (const float*)d_in[11];

    float *pA;
    __nv_bfloat16 *pQh, *pQl, *pKh, *pKl, *pVh, *pVl, *pXhi, *pXlo, *pWhi, *pWlo;
    cudaGetSymbolAddress((void**)&pQh, g_Qhi);
    cudaGetSymbolAddress((void**)&pQl, g_Qlo);
    cudaGetSymbolAddress((void**)&pKh, g_Khi);
    cudaGetSymbolAddress((void**)&pKl, g_Klo);
    cudaGetSymbolAddress((void**)&pVh, g_Vhi);
    cudaGetSymbolAddress((void**)&pVl, g_Vlo);
    cudaGetSymbolAddress((void**)&pA, g_A);
    cudaGetSymbolAddress((void**)&pXhi, g_Xhi);
    cudaGetSymbolAddress((void**)&pXlo, g_Xlo);
    cudaGetSymbolAddress((void**)&pWhi, g_Whi);
    cudaGetSymbolAddress((void**)&pWlo, g_Wlo);

    cudaFuncSetAttribute(gemm_mma_kernel,
                         cudaFuncAttributeMaxDynamicSharedMemorySize, GEMM_SMEM);
    cudaFuncSetAttribute(attn_mma_kernel,
                         cudaFuncAttributeMaxDynamicSharedMemorySize, ATTN_SMEM);

    const int nX4 = CM * CD / 4;
    const int nW4 = CD * CD / 4;
    dim3 gg(CD / 128, CM / 128);          // (8, 32)

    cvt_hilo_kernel<<<nX4 / 256, 256>>>(x, pXhi, pXlo, nX4);

    cvt_hilo_kernel<<<nW4 / 256, 256>>>(Wq, pWhi, pWlo, nW4);
    gemm_mma_kernel<<<gg, 256, GEMM_SMEM>>>(pXhi, pXlo, pWhi, pWlo, bq,
                                            nullptr, pQh, pQl, 1);
    cvt_hilo_kernel<<<nW4 / 256, 256>>>(Wk, pWhi, pWlo, nW4);
    gemm_mma_kernel<<<gg, 256, GEMM_SMEM>>>(pXhi, pXlo, pWhi, pWlo, bk,
                                            nullptr, pKh, pKl, 1);
    cvt_hilo_kernel<<<nW4 / 256, 256>>>(Wv, pWhi, pWlo, nW4);
    gemm_mma_kernel<<<gg, 256, GEMM_SMEM>>>(pXhi, pXlo, pWhi, pWlo, bv,
                                            nullptr, pVh, pVl, 1);

    attn_mma_kernel<<<dim3(CT / 64, CB * CH), 128, ATTN_SMEM>>>(
        dist, sw, pQh, pQl, pKh, pKl, pVh, pVl, pA);

    cvt_hilo_kernel<<<nX4 / 256, 256>>>(pA, pXhi, pXlo, nX4);
    cvt_hilo_kernel<<<nW4 / 256, 256>>>(Wo, pWhi, pWlo, nW4);
    gemm_mma_kernel<<<gg, 256, GEMM_SMEM>>>(pXhi, pXlo, pWhi, pWlo, bo,
                                            (float*)d_out, nullptr, nullptr, 0);
}

// round 16
// speedup vs baseline: 2.7811x; 1.0215x over previous
#include <cuda_runtime.h>
#include <cuda_bf16.h>
#include <math.h>
#include <cstdint>

// Problem constants
#define CB 4
#define CT 1024
#define CD 1024
#define CH 16
#define CDK 64
#define CM (CB * CT)   // 4096 rows

// ---------------------------------------------------------------------------
// Scratch (device globals: allocation-free)
// ---------------------------------------------------------------------------
__device__ __align__(16) __nv_bfloat16 g_Qhi[CB * CH * CT * CDK];
__device__ __align__(16) __nv_bfloat16 g_Qlo[CB * CH * CT * CDK];
__device__ __align__(16) __nv_bfloat16 g_Khi[CB * CH * CT * CDK];
__device__ __align__(16) __nv_bfloat16 g_Klo[CB * CH * CT * CDK];
__device__ __align__(16) __nv_bfloat16 g_Vhi[CB * CH * CT * CDK];
__device__ __align__(16) __nv_bfloat16 g_Vlo[CB * CH * CT * CDK];
__device__ __align__(16) __nv_bfloat16 g_Xhi[CM * CD];      // activations hi/lo
__device__ __align__(16) __nv_bfloat16 g_Xlo[CM * CD];
__device__ __align__(16) __nv_bfloat16 g_Whi[3 * CD * CD];  // stacked weights hi/lo
__device__ __align__(16) __nv_bfloat16 g_Wlo[3 * CD * CD];

// ---------------------------------------------------------------------------
// Baseline-PTX helpers (all legal at compute_103: no arch-'a' features)
// ---------------------------------------------------------------------------
__device__ __forceinline__ uint32_t smem_to_u32(const void* p) {
    uint32_t a;
    asm("{ .reg .u64 t; cvta.to.shared.u64 t, %1; cvt.u32.u64 %0, t; }"
        : "=r"(a) : "l"(p));
    return a;
}
__device__ __forceinline__ void cp16(uint32_t saddr, const void* gptr) {
    asm volatile("cp.async.cg.shared.global [%0], [%1], 16;"
                 :: "r"(saddr), "l"(gptr));
}
#define CP_COMMIT() asm volatile("cp.async.commit_group;" ::: "memory")
#define CP_WAIT_ALL() asm volatile("cp.async.wait_group 0;" ::: "memory")

__device__ __forceinline__ void ldm_x4(uint32_t& r0, uint32_t& r1,
                                       uint32_t& r2, uint32_t& r3, uint32_t addr) {
    asm volatile("ldmatrix.sync.aligned.m8n8.x4.shared.b16 {%0,%1,%2,%3}, [%4];"
                 : "=r"(r0), "=r"(r1), "=r"(r2), "=r"(r3) : "r"(addr));
}
__device__ __forceinline__ void ldm_x4t(uint32_t& r0, uint32_t& r1,
                                        uint32_t& r2, uint32_t& r3, uint32_t addr) {
    asm volatile("ldmatrix.sync.aligned.m8n8.x4.trans.shared.b16 {%0,%1,%2,%3}, [%4];"
                 : "=r"(r0), "=r"(r1), "=r"(r2), "=r"(r3) : "r"(addr));
}
__device__ __forceinline__ void mma_bf16(float& d0, float& d1, float& d2, float& d3,
                                         uint32_t a0, uint32_t a1, uint32_t a2, uint32_t a3,
                                         uint32_t b0, uint32_t b1) {
    asm volatile("mma.sync.aligned.m16n8k16.row.col.f32.bf16.bf16.f32 "
                 "{%0,%1,%2,%3}, {%4,%5,%6,%7}, {%8,%9}, {%0,%1,%2,%3};"
                 : "+f"(d0), "+f"(d1), "+f"(d2), "+f"(d3)
                 : "r"(a0), "r"(a1), "r"(a2), "r"(a3), "r"(b0), "r"(b1));
}
// pack two floats into bf16x2 hi, return lo residual pack
__device__ __forceinline__ uint32_t pk_hilo(float x, float y, uint32_t& lo) {
    __nv_bfloat162 h, l;
    h.x = __float2bfloat16(x); h.y = __float2bfloat16(y);
    l.x = __float2bfloat16(x - __bfloat162float(h.x));
    l.y = __float2bfloat16(y - __bfloat162float(h.y));
    lo = *(uint32_t*)&l;
    return *(uint32_t*)&h;
}

// ---------------------------------------------------------------------------
// fp32 -> (hi, lo) bf16 split, vectorized x4
// ---------------------------------------------------------------------------
__global__ __launch_bounds__(256) void cvt_hilo_kernel(
    const float* __restrict__ src, __nv_bfloat16* __restrict__ hi,
    __nv_bfloat16* __restrict__ lo, int n4)
{
    int i = blockIdx.x * 256 + threadIdx.x;
    if (i >= n4) return;
    float4 v = ((const float4*)src)[i];
    __nv_bfloat162 h0, h1, l0, l1;
    h0.x = __float2bfloat16(v.x); h0.y = __float2bfloat16(v.y);
    h1.x = __float2bfloat16(v.z); h1.y = __float2bfloat16(v.w);
    l0.x = __float2bfloat16(v.x - __bfloat162float(h0.x));
    l0.y = __float2bfloat16(v.y - __bfloat162float(h0.y));
    l1.x = __float2bfloat16(v.z - __bfloat162float(h1.x));
    l1.y = __float2bfloat16(v.w - __bfloat162float(h1.y));
    ((__nv_bfloat162*)hi)[i * 2 + 0] = h0;
    ((__nv_bfloat162*)hi)[i * 2 + 1] = h1;
    ((__nv_bfloat162*)lo)[i * 2 + 0] = l0;
    ((__nv_bfloat162*)lo)[i * 2 + 1] = l1;
}

// ---------------------------------------------------------------------------
// mma.sync GEMM: Y[m,n] = sum_k X[m,k]*W[n,k] + bias[n], hi/lo bf16 3-pass.
// CTA tile M=128, N=128, BK=32. 8 warps, warp tile 32x64 (2x8 m16n8k16).
// grid.z selects weight slice + output set (fused QKV). B-fragment loads
// interleaved with MMAs (keeps live registers low).
// qkv_layout==1: write bf16 hi/lo pair in [B,H,T,DK]; else fp32 [M,N].
// ---------------------------------------------------------------------------
#define ROWB 80                       // 32 bf16 = 64 B data + 16 B pad
#define TILEB (128 * ROWB)            // 10240 B per tile
#define OFF_AHI 0
#define OFF_ALO (1 * TILEB)
#define OFF_BHI (2 * TILEB)
#define OFF_BLO (3 * TILEB)
#define STAGEB  (4 * TILEB)           // 40960 B per stage
#define GEMM_SMEM (2 * STAGEB)        // 81920 B
#define KITERS (CD / 32)              // 32

__global__ __launch_bounds__(256) void gemm_mma_kernel(
    const __nv_bfloat16* __restrict__ Ahi, const __nv_bfloat16* __restrict__ Alo,
    const __nv_bfloat16* __restrict__ Wcat_hi, const __nv_bfloat16* __restrict__ Wcat_lo,
    const float* __restrict__ b0, const float* __restrict__ b1,
    const float* __restrict__ b2, float* __restrict__ Y,
    __nv_bfloat16* __restrict__ Yhi0, __nv_bfloat16* __restrict__ Ylo0,
    __nv_bfloat16* __restrict__ Yhi1, __nv_bfloat16* __restrict__ Ylo1,
    __nv_bfloat16* __restrict__ Yhi2, __nv_bfloat16* __restrict__ Ylo2,
    int qkv_layout)
{
    extern __shared__ char smem[];
    const uint32_t sbase = smem_to_u32(smem);
    const int tid  = threadIdx.x;
    const int wid  = tid >> 5;
    const int lane = tid & 31;
    const int n0 = blockIdx.x * 128;
    const int m0 = blockIdx.y * 128;
    const int z  = blockIdx.z;
    const int warp_m = wid >> 1;
    const int warp_n = wid & 1;

    const float* bias = (z == 0) ? b0 : (z == 1) ? b1 : b2;
    __nv_bfloat16* Yhi = (z == 0) ? Yhi0 : (z == 1) ? Yhi1 : Yhi2;
    __nv_bfloat16* Ylo = (z == 0) ? Ylo0 : (z == 1) ? Ylo1 : Ylo2;
    const __nv_bfloat16* Bhi = Wcat_hi + (size_t)z * CD * CD;
    const __nv_bfloat16* Blo = Wcat_lo + (size_t)z * CD * CD;

    const int s0r = tid >> 2,           s0c = tid & 3;
    const int s1r = (tid + 256) >> 2,   s1c = (tid + 256) & 3;

    const uint4* gA_hi = (const uint4*)Ahi;
    const uint4* gA_lo = (const uint4*)Alo;
    const uint4* gB_hi = (const uint4*)Bhi;
    const uint4* gB_lo = (const uint4*)Blo;
    const int grow = CD / 8;

    auto prefetch = [&](int it, int stage) {
        const int kv4 = it * 4;
        const uint32_t sb = sbase + stage * STAGEB;
        uint32_t sa0 = sb + (uint32_t)(s0r * ROWB + s0c * 16);
        uint32_t sa1 = sb + (uint32_t)(s1r * ROWB + s1c * 16);
        size_t ga0 = (size_t)(m0 + s0r) * grow + kv4 + s0c;
        size_t ga1 = (size_t)(m0 + s1r) * grow + kv4 + s1c;
        size_t gb0 = (size_t)(n0 + s0r) * grow + kv4 + s0c;
        size_t gb1 = (size_t)(n0 + s1r) * grow + kv4 + s1c;
        cp16(sa0 + OFF_AHI, gA_hi + ga0);  cp16(sa1 + OFF_AHI, gA_hi + ga1);
        cp16(sa0 + OFF_ALO, gA_lo + ga0);  cp16(sa1 + OFF_ALO, gA_lo + ga1);
        cp16(sa0 + OFF_BHI, gB_hi + gb0);  cp16(sa1 + OFF_BHI, gB_hi + gb1);
        cp16(sa0 + OFF_BLO, gB_lo + gb0);  cp16(sa1 + OFF_BLO, gB_lo + gb1);
    };

    float acc[2][8][4];
    #pragma unroll
    for (int i = 0; i < 2; ++i)
        #pragma unroll
        for (int j = 0; j < 8; ++j)
            #pragma unroll
            for (int v = 0; v < 4; ++v) acc[i][j][v] = 0.0f;

    const uint32_t a_row = (uint32_t)(warp_m * 32 + (lane & 15));
    const uint32_t a_col = (uint32_t)((lane >> 4) * 16);
    const uint32_t b_rowbase = (uint32_t)(warp_n * 64 + (lane & 7) + ((lane >> 4) << 3));
    const uint32_t b_col = (uint32_t)(((lane >> 3) & 1) * 16);

    prefetch(0, 0);
    CP_COMMIT();

    for (int it = 0; it < KITERS; ++it) {
        CP_WAIT_ALL();
        __syncthreads();
        if (it + 1 < KITERS) { prefetch(it + 1, (it + 1) & 1); CP_COMMIT(); }

        const uint32_t st = sbase + (it & 1) * STAGEB;
        #pragma unroll
        for (int kh = 0; kh < 2; ++kh) {
            const uint32_t kb = (uint32_t)(kh * 32);
            uint32_t ahi[2][4], alo[2][4];
            #pragma unroll
            for (int mt = 0; mt < 2; ++mt) {
                uint32_t addr = st + (a_row + mt * 16) * ROWB + kb + a_col;
                ldm_x4(ahi[mt][0], ahi[mt][1], ahi[mt][2], ahi[mt][3], addr + OFF_AHI);
                ldm_x4(alo[mt][0], alo[mt][1], alo[mt][2], alo[mt][3], addr + OFF_ALO);
            }
            // Interleaved: load one B n-tile pair, use it immediately (low live regs)
            #pragma unroll
            for (int ng = 0; ng < 4; ++ng) {
                uint32_t bh2[2][2], bl2[2][2];
                uint32_t addr = st + (b_rowbase + ng * 16) * ROWB + kb + b_col;
                ldm_x4(bh2[0][0], bh2[0][1], bh2[1][0], bh2[1][1], addr + OFF_BHI);
                ldm_x4(bl2[0][0], bl2[0][1], bl2[1][0], bl2[1][1], addr + OFF_BLO);
                #pragma unroll
                for (int mt = 0; mt < 2; ++mt)
                    #pragma unroll
                    for (int j = 0; j < 2; ++j) {
                        float* d = acc[mt][2 * ng + j];
                        mma_bf16(d[0], d[1], d[2], d[3],
                                 ahi[mt][0], ahi[mt][1], ahi[mt][2], ahi[mt][3],
                                 bh2[j][0], bh2[j][1]);
                        mma_bf16(d[0], d[1], d[2], d[3],
                                 ahi[mt][0], ahi[mt][1], ahi[mt][2], ahi[mt][3],
                                 bl2[j][0], bl2[j][1]);
                        mma_bf16(d[0], d[1], d[2], d[3],
                                 alo[mt][0], alo[mt][1], alo[mt][2], alo[mt][3],
                                 bh2[j][0], bh2[j][1]);
                    }
            }
        }
        __syncthreads();
    }

    // Epilogue
    const int ncolbase = n0 + warp_n * 64;
    const int h  = ncolbase >> 6;
    #pragma unroll
    for (int mt = 0; mt < 2; ++mt) {
        #pragma unroll
        for (int half = 0; half < 2; ++half) {
            int m = m0 + warp_m * 32 + mt * 16 + (lane >> 2) + half * 8;
            if (qkv_layout) {
                int bi = m >> 10, tt = m & 1023;
                size_t base = ((size_t)(bi * CH + h) * CT + tt) * CDK;
                #pragma unroll
                for (int nt = 0; nt < 8; ++nt) {
                    int c = nt * 8 + (lane & 3) * 2;
                    float y0 = acc[mt][nt][half * 2 + 0] + bias[ncolbase + c + 0];
                    float y1 = acc[mt][nt][half * 2 + 1] + bias[ncolbase + c + 1];
                    uint32_t lo, hi = pk_hilo(y0, y1, lo);
                    *(uint32_t*)(Yhi + base + c) = hi;
                    *(uint32_t*)(Ylo + base + c) = lo;
                }
            } else {
                float* dst = Y + (size_t)m * CD + ncolbase;
                #pragma unroll
                for (int nt = 0; nt < 8; ++nt) {
                    int c = nt * 8 + (lane & 3) * 2;
                    float2 o;
                    o.x = acc[mt][nt][half * 2 + 0] + bias[ncolbase + c + 0];
                    o.y = acc[mt][nt][half * 2 + 1] + bias[ncolbase + c + 1];
                    *(float2*)(dst + c) = o;
                }
            }
        }
    }
}

// ----------------------------------------------------------------------------
// mma.sync flash attention, hi/lo bf16 3-pass for QK^T and PV.
// Br=Bc=64, 4 warps (128 thr); warp w owns rows w*16..w*16+15 (all 64 cols).
// Attention tiles are 64x64 bf16 = 128 B/row -> AROWB=144 (128 data + 16 pad).
// cp.async double-buffered K/V hi/lo tiles. Causal; spatial bias from gmem.
// Output written as bf16 hi/lo directly into the activation buffers [B,T,D].
// ----------------------------------------------------------------------------
#define AROWB 144                     // 64 bf16 = 128 B data + 16 B pad
#define ATILEB (64 * AROWB)           // 9216
#define ASM_QHI 0
#define ASM_QLO ATILEB
#define ASM_KV  (2 * ATILEB)          // 18432
#define AST_KHI 0
#define AST_KLO (1 * ATILEB)
#define AST_VHI (2 * ATILEB)
#define AST_VLO (3 * ATILEB)
#define ASTAGEB (4 * ATILEB)          // 36864
#define ATTN_SMEM (2 * ATILEB + 2 * ASTAGEB)   // 92160

__global__ __launch_bounds__(128) void attn_mma_kernel(
    const float* __restrict__ dist, const float* __restrict__ swp,
    const __nv_bfloat16* __restrict__ Qhi, const __nv_bfloat16* __restrict__ Qlo,
    const __nv_bfloat16* __restrict__ Khi, const __nv_bfloat16* __restrict__ Klo,
    const __nv_bfloat16* __restrict__ Vhi, const __nv_bfloat16* __restrict__ Vlo,
    __nv_bfloat16* __restrict__ Ahi_out, __nv_bfloat16* __restrict__ Alo_out)
{
    extern __shared__ char smem[];
    const uint32_t sbase = smem_to_u32(smem);
    const int tid  = threadIdx.x;
    const int wid  = tid >> 5;
    const int lane = tid & 31;
    const int qt = blockIdx.x;
    const int bh = blockIdx.y;
    const int b  = bh >> 4;
    const int h  = bh & 15;
    const int qbase = qt * 64;
    const float alpha = fabsf(swp[0]);

    auto prefetch_kv = [&](int jt, int stage) {
        const uint32_t sb = sbase + ASM_KV + stage * ASTAGEB;
        const int kb = jt * 64;
        #pragma unroll
        for (int i = 0; i < 4; ++i) {
            int slot = tid + i * 128;         // 0..511
            int row = slot >> 3, c16 = slot & 7;
            uint32_t sa = sb + (uint32_t)(row * AROWB + c16 * 16);
            size_t g = ((size_t)bh * CT + kb + row) * (CDK / 8) + c16;
            cp16(sa + AST_KHI, (const uint4*)Khi + g);
            cp16(sa + AST_KLO, (const uint4*)Klo + g);
            cp16(sa + AST_VHI, (const uint4*)Vhi + g);
            cp16(sa + AST_VLO, (const uint4*)Vlo + g);
        }
    };

    // Q tile load + first KV stage
    #pragma unroll
    for (int i = 0; i < 4; ++i) {
        int slot = tid + i * 128;
        int row = slot >> 3, c16 = slot & 7;
        uint32_t sa = sbase + (uint32_t)(row * AROWB + c16 * 16);
        size_t g = ((size_t)bh * CT + qbase + row) * (CDK / 8) + c16;
        cp16(sa + ASM_QHI, (const uint4*)Qhi + g);
        cp16(sa + ASM_QLO, (const uint4*)Qlo + g);
    }
    prefetch_kv(0, 0);
    CP_COMMIT();

    // fragment address components
    const uint32_t a_row = (uint32_t)(wid * 16 + (lane & 15));
    const uint32_t a_col = (uint32_t)((lane >> 4) * 16);
    const uint32_t b_rowbase = (uint32_t)((lane & 7) + ((lane >> 4) << 3));
    const uint32_t b_col = (uint32_t)(((lane >> 3) & 1) * 16);
    const uint32_t v_row = (uint32_t)(lane & 15);
    const uint32_t v_col = (uint32_t)((lane >> 4) * 16);

    uint32_t qhi[4][4], qlo[4][4];
    float oacc[8][4];
    #pragma unroll
    for (int nt = 0; nt < 8; ++nt)
        #pragma unroll
        for (int v = 0; v < 4; ++v) oacc[nt][v] = 0.0f;
    float m0 = -1e30f, m1 = -1e30f, l0 = 0.0f, l1 = 0.0f;

    const int r0 = lane >> 2;
    const int cbase = (lane & 3) * 2;
    const int row0g = qbase + wid * 16 + r0;
    const float* distrow0 = dist + ((size_t)b * CT + row0g) * CT;
    const float* distrow1 = distrow0 + 8 * CT;

    for (int jt = 0; jt <= qt; ++jt) {
        CP_WAIT_ALL();
        __syncthreads();
        if (jt == 0) {
            #pragma unroll
            for (int ks = 0; ks < 4; ++ks) {
                uint32_t addr = sbase + a_row * AROWB + ks * 32 + a_col;
                ldm_x4(qhi[ks][0], qhi[ks][1], qhi[ks][2], qhi[ks][3], addr + ASM_QHI);
                ldm_x4(qlo[ks][0], qlo[ks][1], qlo[ks][2], qlo[ks][3], addr + ASM_QLO);
            }
        }
        if (jt + 1 <= qt) { prefetch_kv(jt + 1, (jt + 1) & 1); CP_COMMIT(); }

        const uint32_t st = sbase + ASM_KV + (jt & 1) * ASTAGEB;

        // ---- S = Q K^T (hi/lo 3-pass) ----
        float sacc[8][4];
        #pragma unroll
        for (int nt = 0; nt < 8; ++nt)
            #pragma unroll
            for (int v = 0; v < 4; ++v) sacc[nt][v] = 0.0f;

        #pragma unroll
        for (int ks = 0; ks < 4; ++ks) {
            uint32_t kh[8][2], kl[8][2];
            #pragma unroll
            for (int ng = 0; ng < 4; ++ng) {
                uint32_t addr = st + (b_rowbase + ng * 16) * AROWB + ks * 32 + b_col;
                ldm_x4(kh[2 * ng][0], kh[2 * ng][1], kh[2 * ng + 1][0],
                       kh[2 * ng + 1][1], addr + AST_KHI);
                ldm_x4(kl[2 * ng][0], kl[2 * ng][1], kl[2 * ng + 1][0],
                       kl[2 * ng + 1][1], addr + AST_KLO);
            }
            #pragma unroll
            for (int nt = 0; nt < 8; ++nt) {
                float* d = sacc[nt];
                mma_bf16(d[0], d[1], d[2], d[3],
                         qhi[ks][0], qhi[ks][1], qhi[ks][2], qhi[ks][3],
                         kh[nt][0], kh[nt][1]);
                mma_bf16(d[0], d[1], d[2], d[3],
                         qhi[ks][0], qhi[ks][1], qhi[ks][2], qhi[ks][3],
                         kl[nt][0], kl[nt][1]);
                mma_bf16(d[0], d[1], d[2], d[3],
                         qlo[ks][0], qlo[ks][1], qlo[ks][2], qlo[ks][3],
                         kh[nt][0], kh[nt][1]);
            }
        }

        // ---- bias + causal mask + online softmax ----
        const bool diag = (jt == qt);
        const int kbase = jt * 64;
        const int rw0 = wid * 16 + r0;
        const int rw1 = rw0 + 8;
        float p[8][4];
        float mx0 = -1e30f, mx1 = -1e30f;
        #pragma unroll
        for (int nt = 0; nt < 8; ++nt) {
            int c = nt * 8 + cbase;
            float2 dv0 = *(const float2*)(distrow0 + kbase + c);
            float2 dv1 = *(const float2*)(distrow1 + kbase + c);
            float s0 = sacc[nt][0] * 0.125f - alpha * dv0.x;
            float s1 = sacc[nt][1] * 0.125f - alpha * dv0.y;
            float s2 = sacc[nt][2] * 0.125f - alpha * dv1.x;
            float s3 = sacc[nt][3] * 0.125f - alpha * dv1.y;
            if (diag) {
                if (c     > rw0) s0 = -1e30f;
                if (c + 1 > rw0) s1 = -1e30f;
                if (c     > rw1) s2 = -1e30f;
                if (c + 1 > rw1) s3 = -1e30f;
            }
            p[nt][0] = s0; p[nt][1] = s1; p[nt][2] = s2; p[nt][3] = s3;
            mx0 = fmaxf(mx0, fmaxf(s0, s1));
            mx1 = fmaxf(mx1, fmaxf(s2, s3));
        }
        mx0 = fmaxf(mx0, __shfl_xor_sync(0xffffffffu, mx0, 1));
        mx0 = fmaxf(mx0, __shfl_xor_sync(0xffffffffu, mx0, 2));
        mx1 = fmaxf(mx1, __shfl_xor_sync(0xffffffffu, mx1, 1));
        mx1 = fmaxf(mx1, __shfl_xor_sync(0xffffffffu, mx1, 2));
        float mn0 = fmaxf(m0, mx0), mn1 = fmaxf(m1, mx1);
        float corr0 = __expf(m0 - mn0), corr1 = __expf(m1 - mn1);
        float sum0 = 0.0f, sum1 = 0.0f;
        #pragma unroll
        for (int nt = 0; nt < 8; ++nt) {
            p[nt][0] = __expf(p[nt][0] - mn0);
            p[nt][1] = __expf(p[nt][1] - mn0);
            p[nt][2] = __expf(p[nt][2] - mn1);
            p[nt][3] = __expf(p[nt][3] - mn1);
            sum0 += p[nt][0] + p[nt][1];
            sum1 += p[nt][2] + p[nt][3];
        }
        sum0 += __shfl_xor_sync(0xffffffffu, sum0, 1);
        sum0 += __shfl_xor_sync(0xffffffffu, sum0, 2);
        sum1 += __shfl_xor_sync(0xffffffffu, sum1, 1);
        sum1 += __shfl_xor_sync(0xffffffffu, sum1, 2);
        l0 = l0 * corr0 + sum0;  l1 = l1 * corr1 + sum1;
        m0 = mn0;  m1 = mn1;
        #pragma unroll
        for (int nt = 0; nt < 8; ++nt) {
            oacc[nt][0] *= corr0; oacc[nt][1] *= corr0;
            oacc[nt][2] *= corr1; oacc[nt][3] *= corr1;
        }

        // ---- P -> A fragments (hi/lo), direct from registers ----
        uint32_t pah[4][4], pal[4][4];
        #pragma unroll
        for (int ks = 0; ks < 4; ++ks) {
            pah[ks][0] = pk_hilo(p[2 * ks][0],     p[2 * ks][1],     pal[ks][0]);
            pah[ks][1] = pk_hilo(p[2 * ks][2],     p[2 * ks][3],     pal[ks][1]);
            pah[ks][2] = pk_hilo(p[2 * ks + 1][0], p[2 * ks + 1][1], pal[ks][2]);
            pah[ks][3] = pk_hilo(p[2 * ks + 1][2], p[2 * ks + 1][3], pal[ks][3]);
        }

        // ---- O += P V (hi/lo 3-pass), V via ldmatrix.trans ----
        #pragma unroll
        for (int ks = 0; ks < 4; ++ks) {
            uint32_t vh[8][2], vl[8][2];
            #pragma unroll
            for (int ng = 0; ng < 4; ++ng) {
                uint32_t addr = st + (ks * 16 + v_row) * AROWB + ng * 32 + v_col;
                ldm_x4t(vh[2 * ng][0], vh[2 * ng][1], vh[2 * ng + 1][0],
                        vh[2 * ng + 1][1], addr + AST_VHI);
                ldm_x4t(vl[2 * ng][0], vl[2 * ng][1], vl[2 * ng + 1][0],
                        vl[2 * ng + 1][1], addr + AST_VLO);
            }
            #pragma unroll
            for (int nt = 0; nt < 8; ++nt) {
                float* d = oacc[nt];
                mma_bf16(d[0], d[1], d[2], d[3],
                         pah[ks][0], pah[ks][1], pah[ks][2], pah[ks][3],
                         vh[nt][0], vh[nt][1]);
                mma_bf16(d[0], d[1], d[2], d[3],
                         pal[ks][0], pal[ks][1], pal[ks][2], pal[ks][3],
                         vh[nt][0], vh[nt][1]);
                mma_bf16(d[0], d[1], d[2], d[3],
                         pah[ks][0], pah[ks][1], pah[ks][2], pah[ks][3],
                         vl[nt][0], vl[nt][1]);
            }
        }
        __syncthreads();
    }

    // ---- normalize + write bf16 hi/lo into activation buffers [B,T,D] ----
    const float linv0 = 1.0f / l0, linv1 = 1.0f / l1;
    const int t0 = qbase + wid * 16 + r0;
    size_t base0 = ((size_t)b * CT + t0) * CD + h * 64;
    size_t base1 = base0 + (size_t)8 * CD;
    #pragma unroll
    for (int nt = 0; nt < 8; ++nt) {
        int c = nt * 8 + cbase;
        uint32_t lo0, hi0 = pk_hilo(oacc[nt][0] * linv0, oacc[nt][1] * linv0, lo0);
        uint32_t lo1, hi1 = pk_hilo(oacc[nt][2] * linv1, oacc[nt][3] * linv1, lo1);
        *(uint32_t*)(Ahi_out + base0 + c) = hi0;
        *(uint32_t*)(Alo_out + base0 + c) = lo0;
        *(uint32_t*)(Ahi_out + base1 + c) = hi1;
        *(uint32_t*)(Alo_out + base1 + c) = lo1;
    }
}

// ----------------------------------------------------------------------------
// Launch
// Inputs: x, s2_distances, mask, Wq, bq, Wk, bk, Wv, bv, Wo, bo, spatial_weight
// ----------------------------------------------------------------------------
extern "C" void kernel_launch(void* const* d_in, const int* in_sizes, int n_in,
                              void* d_out, int out_size)
{
    (void)in_sizes; (void)n_in; (void)out_size;
    const float* x    = (const float*)d_in[0];
    const float* dist = (const float*)d_in[1];
    const float* Wq = (const float*)d_in[3];
    const float* bq = (const float*)d_in[4];
    const float* Wk = (const float*)d_in[5];
    const float* bk = (const float*)d_in[6];
    const float* Wv = (const float*)d_in[7];
    const float* bv = (const float*)d_in[8];
    const float* Wo = (const float*)d_in[9];
    const float* bo = (const float*)d_in[10];
    const float* sw = (const float*)d_in[11];

    __nv_bfloat16 *pQh, *pQl, *pKh, *pKl, *pVh, *pVl, *pXhi, *pXlo, *pWhi, *pWlo;
    cudaGetSymbolAddress((void**)&pQh, g_Qhi);
    cudaGetSymbolAddress((void**)&pQl, g_Qlo);
    cudaGetSymbolAddress((void**)&pKh, g_Khi);
    cudaGetSymbolAddress((void**)&pKl, g_Klo);
    cudaGetSymbolAddress((void**)&pVh, g_Vhi);
    cudaGetSymbolAddress((void**)&pVl, g_Vlo);
    cudaGetSymbolAddress((void**)&pXhi, g_Xhi);
    cudaGetSymbolAddress((void**)&pXlo, g_Xlo);
    cudaGetSymbolAddress((void**)&pWhi, g_Whi);
    cudaGetSymbolAddress((void**)&pWlo, g_Wlo);

    cudaFuncSetAttribute(gemm_mma_kernel,
                         cudaFuncAttributeMaxDynamicSharedMemorySize, GEMM_SMEM);
    cudaFuncSetAttribute(attn_mma_kernel,
                         cudaFuncAttributeMaxDynamicSharedMemorySize, ATTN_SMEM);

    const int nX4 = CM * CD / 4;
    const int nW4 = CD * CD / 4;
    const size_t wslice = (size_t)CD * CD;

    // X -> hi/lo
    cvt_hilo_kernel<<<nX4 / 256, 256>>>(x, pXhi, pXlo, nX4);

    // Wq/Wk/Wv -> stacked hi/lo slices
    cvt_hilo_kernel<<<nW4 / 256, 256>>>(Wq, pWhi,              pWlo,              nW4);
    cvt_hilo_kernel<<<nW4 / 256, 256>>>(Wk, pWhi + wslice,     pWlo + wslice,     nW4);
    cvt_hilo_kernel<<<nW4 / 256, 256>>>(Wv, pWhi + 2 * wslice, pWlo + 2 * wslice, nW4);

    // Fused QKV projection (grid.z selects head matrix)
    gemm_mma_kernel<<<dim3(CD / 128, CM / 128, 3), 256, GEMM_SMEM>>>(
        pXhi, pXlo, pWhi, pWlo, bq, bk, bv, nullptr,
        pQh, pQl, pKh, pKl, pVh, pVl, 1);

    // Attention -> writes bf16 hi/lo activations directly
    attn_mma_kernel<<<dim3(CT / 64, CB * CH), 128, ATTN_SMEM>>>(
        dist, sw, pQh, pQl, pKh, pKl, pVh, pVl, pXhi, pXlo);

    // Wo -> slice 0, then output projection (fp32 out)
    cvt_hilo_kernel<<<nW4 / 256, 256>>>(Wo, pWhi, pWlo, nW4);
    gemm_mma_kernel<<<dim3(CD / 128, CM / 128, 1), 256, GEMM_SMEM>>>(
        pXhi, pXlo, pWhi, pWlo, bo, nullptr, nullptr, (float*)d_out,
        nullptr, nullptr, nullptr, nullptr, nullptr, nullptr, 0);
}